// round 1
// baseline (speedup 1.0000x reference)
#include <cuda_runtime.h>
#include <math.h>

// Analytic collapse of the product-state quantum circuit:
//   encoded[b,j] = dot(x[b,:], enc_w[j,:]) + enc_b[j]          (j = gate-qubit)
//   Theta[j]     = sum_{d<4} theta[d*16 + j]                   (Ry's compose)
//   m[b,j]       = cos(Theta[j]) * cos(encoded[b,j])           (<Z> of 2-level system)
//   exp_vals[b,q]= m[b, 15-q]                                  (bit-order swap)
//   logits[b,c]  = sum_q exp_vals[b,q]*cls_w[c,q] + cls_b[c]
//               = sum_j m[b,j]*cls_w[c, 15-j] + cls_b[c]

#define NQ 16
#define NF 512
#define NC 10

__global__ __launch_bounds__(512, 2)
void hybrid_fcl_fused(const float* __restrict__ x,
                      const float* __restrict__ enc_w,
                      const float* __restrict__ enc_b,
                      const float* __restrict__ theta,
                      const float* __restrict__ cls_w,
                      const float* __restrict__ cls_b,
                      float* __restrict__ out)
{
    const int b    = blockIdx.x;        // batch row
    const int w    = threadIdx.x >> 5;  // warp id = gate-qubit j (0..15)
    const int lane = threadIdx.x & 31;

    // 512-feature dot product: 4 float4 per lane, 16 warps in parallel (one per qubit)
    const float4* __restrict__ xr = reinterpret_cast<const float4*>(x + (size_t)b * NF);
    const float4* __restrict__ wr = reinterpret_cast<const float4*>(enc_w + (size_t)w * NF);

    float acc = 0.0f;
#pragma unroll
    for (int i = 0; i < 4; ++i) {
        float4 a = xr[lane + 32 * i];
        float4 c = wr[lane + 32 * i];
        acc = fmaf(a.x, c.x, acc);
        acc = fmaf(a.y, c.y, acc);
        acc = fmaf(a.z, c.z, acc);
        acc = fmaf(a.w, c.w, acc);
    }
    // warp tree-reduce
#pragma unroll
    for (int off = 16; off; off >>= 1)
        acc += __shfl_xor_sync(0xFFFFFFFFu, acc, off);

    __shared__ float m[NQ];
    if (lane == 0) {
        float enc = acc + enc_b[w];
        float Th  = theta[w] + theta[NQ + w] + theta[2 * NQ + w] + theta[3 * NQ + w];
        m[w] = cosf(Th) * cosf(enc);
    }
    __syncthreads();

    // 10 logits per batch row
    if (threadIdx.x < NC) {
        const int c = threadIdx.x;
        float s = cls_b[c];
#pragma unroll
        for (int j = 0; j < NQ; ++j)
            s = fmaf(m[j], cls_w[c * NQ + (NQ - 1 - j)], s);
        out[(size_t)b * NC + c] = s;
    }
}

extern "C" void kernel_launch(void* const* d_in, const int* in_sizes, int n_in,
                              void* d_out, int out_size)
{
    const float* x     = (const float*)d_in[0]; // (256, 512)
    const float* enc_w = (const float*)d_in[1]; // (16, 512)
    const float* enc_b = (const float*)d_in[2]; // (16,)
    const float* theta = (const float*)d_in[3]; // (64,)
    const float* cls_w = (const float*)d_in[4]; // (10, 16)
    const float* cls_b = (const float*)d_in[5]; // (10,)
    float* out = (float*)d_out;                 // (256, 10)

    const int batch = in_sizes[0] / NF;         // 256
    hybrid_fcl_fused<<<batch, 512>>>(x, enc_w, enc_b, theta, cls_w, cls_b, out);
}

// round 2
// speedup vs baseline: 1.0388x; 1.0388x over previous
#include <cuda_runtime.h>
#include <math.h>

// Analytic collapse of the product-state quantum circuit:
//   encoded[b,j] = dot(x[b,:], enc_w[j,:]) + enc_b[j]          (j = gate-qubit)
//   Theta[j]     = sum_{d<4} theta[d*16 + j]                   (Ry's compose)
//   m[b,j]       = cos(Theta[j]) * cos(encoded[b,j])           (<Z> of 2-level system)
//   logits[b,c]  = sum_j m[b,j]*cls_w[c, 15-j] + cls_b[c]      (bit-order swap folded)
//
// Latency-bound kernel: all constant loads are prefetched at entry so their
// first-touch L2 latency overlaps the x-row DRAM miss; the only post-reduce
// chain is MUFU cos -> STS -> BAR -> LDS -> 16 FMA -> STG.

#define NQ 16
#define NF 512
#define NC 10

__global__ __launch_bounds__(512, 2)
void hybrid_fcl_fused(const float* __restrict__ x,
                      const float* __restrict__ enc_w,
                      const float* __restrict__ enc_b,
                      const float* __restrict__ theta,
                      const float* __restrict__ cls_w,
                      const float* __restrict__ cls_b,
                      float* __restrict__ out)
{
    const int b    = blockIdx.x;        // batch row
    const int w    = threadIdx.x >> 5;  // warp id = gate-qubit j (0..15)
    const int lane = threadIdx.x & 31;
    const int tid  = threadIdx.x;

    // ---- prefetch phase-2 constants (overlaps the x DRAM miss) ----
    float4 cw0, cw1, cw2, cw3;          // cls_w row for class c = tid (tid < 10)
    float  cb = 0.0f;
    if (tid < NC) {
        const float4* cwr = reinterpret_cast<const float4*>(cls_w + tid * NQ);
        cw0 = cwr[0]; cw1 = cwr[1]; cw2 = cwr[2]; cw3 = cwr[3];
        cb  = cls_b[tid];
    }

    // ---- prefetch lane0 constants + hoist cos(Theta) off the critical path ----
    float cosTh = 0.0f, eb = 0.0f;
    if (lane == 0) {
        eb = enc_b[w];
        float Th = theta[w] + theta[NQ + w] + theta[2 * NQ + w] + theta[3 * NQ + w];
        cosTh = __cosf(Th);
    }

    // ---- 512-feature dot: 4 float4 per lane, 16 warps (one per qubit) ----
    const float4* __restrict__ xr = reinterpret_cast<const float4*>(x + (size_t)b * NF);
    const float4* __restrict__ wr = reinterpret_cast<const float4*>(enc_w + (size_t)w * NF);

    float4 a0 = xr[lane];       float4 c0 = wr[lane];
    float4 a1 = xr[lane + 32];  float4 c1 = wr[lane + 32];
    float4 a2 = xr[lane + 64];  float4 c2 = wr[lane + 64];
    float4 a3 = xr[lane + 96];  float4 c3 = wr[lane + 96];

    // two accumulator chains to halve the FMA dependency depth
    float p0 = 0.0f, p1 = 0.0f;
    p0 = fmaf(a0.x, c0.x, p0); p1 = fmaf(a0.y, c0.y, p1);
    p0 = fmaf(a0.z, c0.z, p0); p1 = fmaf(a0.w, c0.w, p1);
    p0 = fmaf(a1.x, c1.x, p0); p1 = fmaf(a1.y, c1.y, p1);
    p0 = fmaf(a1.z, c1.z, p0); p1 = fmaf(a1.w, c1.w, p1);
    p0 = fmaf(a2.x, c2.x, p0); p1 = fmaf(a2.y, c2.y, p1);
    p0 = fmaf(a2.z, c2.z, p0); p1 = fmaf(a2.w, c2.w, p1);
    p0 = fmaf(a3.x, c3.x, p0); p1 = fmaf(a3.y, c3.y, p1);
    p0 = fmaf(a3.z, c3.z, p0); p1 = fmaf(a3.w, c3.w, p1);
    float acc = p0 + p1;

    // warp tree-reduce
#pragma unroll
    for (int off = 16; off; off >>= 1)
        acc += __shfl_xor_sync(0xFFFFFFFFu, acc, off);

    __shared__ float m[NQ];
    if (lane == 0)
        m[w] = cosTh * __cosf(acc + eb);   // single MUFU on the post-reduce path
    __syncthreads();

    // ---- 10 logits, everything except m[] already in registers ----
    if (tid < NC) {
        const float4* ms = reinterpret_cast<const float4*>(m);
        float4 m0 = ms[0], m1 = ms[1], m2 = ms[2], m3 = ms[3];
        // logits[c] = cb + sum_j m[j] * cls_w[c, 15-j]
        float s = cb;
        s = fmaf(m0.x, cw3.w, s); s = fmaf(m0.y, cw3.z, s);
        s = fmaf(m0.z, cw3.y, s); s = fmaf(m0.w, cw3.x, s);
        s = fmaf(m1.x, cw2.w, s); s = fmaf(m1.y, cw2.z, s);
        s = fmaf(m1.z, cw2.y, s); s = fmaf(m1.w, cw2.x, s);
        s = fmaf(m2.x, cw1.w, s); s = fmaf(m2.y, cw1.z, s);
        s = fmaf(m2.z, cw1.y, s); s = fmaf(m2.w, cw1.x, s);
        s = fmaf(m3.x, cw0.w, s); s = fmaf(m3.y, cw0.z, s);
        s = fmaf(m3.z, cw0.y, s); s = fmaf(m3.w, cw0.x, s);
        out[(size_t)b * NC + tid] = s;
    }
}

extern "C" void kernel_launch(void* const* d_in, const int* in_sizes, int n_in,
                              void* d_out, int out_size)
{
    const float* x     = (const float*)d_in[0]; // (256, 512)
    const float* enc_w = (const float*)d_in[1]; // (16, 512)
    const float* enc_b = (const float*)d_in[2]; // (16,)
    const float* theta = (const float*)d_in[3]; // (64,)
    const float* cls_w = (const float*)d_in[4]; // (10, 16)
    const float* cls_b = (const float*)d_in[5]; // (10,)
    float* out = (float*)d_out;                 // (256, 10)

    const int batch = in_sizes[0] / NF;         // 256
    hybrid_fcl_fused<<<batch, 512>>>(x, enc_w, enc_b, theta, cls_w, cls_b, out);
}